// round 16
// baseline (speedup 1.0000x reference)
#include <cuda_runtime.h>

// ============================================================================
// Compile-time Clebsch-Gordan / real Wigner-3j tables.
// Bit-for-bit replication of the reference's Racah formula + e3nn real basis
// change, evaluated in constexpr doubles, so every coefficient becomes an
// immediate in SASS and zero entries are eliminated at compile time.
// ============================================================================
namespace cgc {

constexpr double cfact(int n){ double r=1.0; for(int i=2;i<=n;i++) r*=(double)i; return r; }
constexpr double csqrt(double x){
  if(x<=0.0) return 0.0;
  double r = x>1.0? x:1.0;
  for(int i=0;i<60;i++) r = 0.5*(r + x/r);
  return r;
}
constexpr int cmax3(int a,int b,int c){ int m=a>b?a:b; return m>c?m:c; }
constexpr int cmin3(int a,int b,int c){ int m=a<b?a:b; return m<c?m:c; }

constexpr double su2_cg(int j1,int m1,int j2,int m2,int j3,int m3){
  if(m3 != m1+m2) return 0.0;
  int vmin = cmax3(-j1+j2+m3, -j1+m1, 0);
  int vmax = cmin3(j2+j3+m1, j3-j1+j2, j3+m3);
  if(vmax < vmin) return 0.0;
  double C = csqrt((double)(2*j3+1)*cfact(j3+j1-j2)*cfact(j3-j1+j2)*cfact(j1+j2-j3)
                   *cfact(j3+m3)*cfact(j3-m3)
                   /(cfact(j1+j2+j3+1)*cfact(j1-m1)*cfact(j1+m1)*cfact(j2-m2)*cfact(j2+m2)));
  double S=0.0;
  for(int v=vmin; v<=vmax; v++){
    double sgn = ((v+j2+m2)&1)? -1.0: 1.0;
    S += sgn/cfact(v)*cfact(j2+j3+m1-v)*cfact(j1-m1+v)
         /(cfact(j3-j1+j2-v)*cfact(j3+m3-v)*cfact(v+j1-j2-m3));
  }
  return C*S;
}

struct cplx { double re; double im; };
constexpr cplx cmul(cplx a, cplx b){ return cplx{a.re*b.re-a.im*b.im, a.re*b.im+a.im*b.re}; }
constexpr cplx conjc(cplx a){ return cplx{a.re,-a.im}; }

// Sized for max l = 4 (2*l+1 = 9): qmat is used for l1,l2 (<=2) AND l3 (<=4).
struct QMat { cplx v[9][9]; };
constexpr QMat qmat(int l){
  QMat q{};
  double s = 1.0/csqrt(2.0);
  for(int m=-l;m<0;m++){
    q.v[l+m][l-m] = cplx{s,0.0};      // q[l+m, l+|m|] = s
    q.v[l+m][l+m] = cplx{0.0,-s};     // q[l+m, l-|m|] = -i s
  }
  q.v[l][l] = cplx{1.0,0.0};
  for(int m=1;m<=l;m++){
    double sg = (m&1)? -1.0:1.0;
    q.v[l+m][l+m] = cplx{sg*s,0.0};
    q.v[l+m][l-m] = cplx{0.0,sg*s};
  }
  cplx ph{1.0,0.0};
  for(int i=0;i<l;i++) ph = cmul(ph, cplx{0.0,-1.0});   // (-1j)^l
  for(int a=0;a<2*l+1;a++) for(int b=0;b<2*l+1;b++) q.v[a][b] = cmul(ph, q.v[a][b]);
  return q;
}

struct W3J { double v[5][5][9]; };

constexpr W3J wigner3j_scaled(int l1,int l2,int l3){
  cplx C[5][5][9] = {};
  for(int m1=-l1;m1<=l1;m1++)
    for(int m2=-l2;m2<=l2;m2++){
      int m3=m1+m2;
      if(m3>=-l3 && m3<=l3)
        C[l1+m1][l2+m2][l3+m3] = cplx{ su2_cg(l1,m1,l2,m2,l3,m3), 0.0 };
    }
  QMat q1=qmat(l1); QMat q2=qmat(l2); QMat q3=qmat(l3);
  W3J R{};
  double norm2=0.0;
  for(int j=0;j<2*l1+1;j++)
   for(int l=0;l<2*l2+1;l++)
    for(int n=0;n<2*l3+1;n++){
      double sre=0.0;
      for(int i=0;i<2*l1+1;i++){
        if(q1.v[i][j].re==0.0 && q1.v[i][j].im==0.0) continue;
        for(int k=0;k<2*l2+1;k++){
          if(q2.v[k][l].re==0.0 && q2.v[k][l].im==0.0) continue;
          for(int m=0;m<2*l3+1;m++){
            double cr = C[i][k][m].re;
            if(cr==0.0) continue;
            cplx t = cmul(cmul(q1.v[i][j], q2.v[k][l]), conjc(q3.v[m][n]));
            sre += t.re*cr;
          }
        }
      }
      R.v[j][l][n]=sre;
      norm2 += sre*sre;
    }
  double sc = csqrt((double)(2*l3+1))/csqrt(norm2);  // unit-Frobenius, then *sqrt(2l3+1)
  for(int j=0;j<2*l1+1;j++) for(int l=0;l<2*l2+1;l++) for(int n=0;n<2*l3+1;n++)
    R.v[j][l][n]*=sc;
  return R;
}

struct AllCG { W3J p[19]; };
constexpr AllCG build_all(){
  AllCG A{};
  int idx=0;
  for(int l1=0;l1<3;l1++)
    for(int l2=0;l2<3;l2++){
      int lo = l1>l2? l1-l2 : l2-l1;
      for(int l3=lo;l3<=l1+l2;l3++){
        A.p[idx] = wigner3j_scaled(l1,l2,l3);
        idx++;
      }
    }
  return A;
}
constexpr AllCG CG_ALL = build_all();

} // namespace cgc

// Output chunk offsets per path index (e3nn Irreps.sort order of output, precomputed):
// order = [0,4,14, 1,3,7,11,5,15, 2,6,10,16,8,12, 9,13,17, 18], chunk = 32*(2l3+1)
constexpr int OUT_OFF[19] = {0,96,672,192,32,480,832,288,1312,1632,
                             992,384,1472,1856,64,576,1152,2080,2304};

template<int P,int M,int Nn,int O>
__host__ __device__ constexpr float cgf(){
  constexpr double v = cgc::CG_ALL.p[P].v[M][Nn][O];
  return (v>1e-7 || v<-1e-7) ? (float)v : 0.0f;
}

// ---- compile-time loop machinery (indices stay constant expressions) ----
template<int I> struct ic { static constexpr int value = I; };
template<int N,int I=0,class F>
__device__ __forceinline__ void static_for(F&& f){
  if constexpr (I < N){ f(ic<I>{}); static_for<N, I+1>(f); }
}

// One (l1,l2) block: compute all l3 paths, stage strided outputs through SMEM
// (lane-stride d3 is odd -> bank-conflict-free), store coalesced.
template<int L1,int L2,int P0>
__device__ __forceinline__ void do_block(const float (&a)[9], const float (&b)[9],
                                         float* __restrict__ outRow,
                                         float* st, int lane){
  constexpr int D1 = 2*L1+1, D2 = 2*L2+1;
  constexpr int AO = (L1==0)?0:((L1==1)?1:4);
  constexpr int BO = (L2==0)?0:((L2==1)?1:4);
  float p[D1*D2];
  static_for<D1*D2>([&](auto mn){
    constexpr int MN = decltype(mn)::value;
    p[MN] = a[AO + MN/D2] * b[BO + MN%D2];
  });
  constexpr int L3LO = (L1>L2)?(L1-L2):(L2-L1);
  static_for<L1+L2-L3LO+1>([&](auto t){
    constexpr int T  = decltype(t)::value;
    constexpr int L3 = L3LO + T;
    constexpr int P  = P0 + T;
    constexpr int D3 = 2*L3+1;
    constexpr int OFF = OUT_OFF[P];
    float acc[D3] = {};
    static_for<D1>([&](auto mi){
      constexpr int M = decltype(mi)::value;
      static_for<D2>([&](auto ni){
        constexpr int Nn = decltype(ni)::value;
        static_for<D3>([&](auto oi){
          constexpr int O = decltype(oi)::value;
          constexpr float c = cgf<P,M,Nn,O>();
          if constexpr (c != 0.0f)
            acc[O] = fmaf(c, p[M*D2+Nn], acc[O]);
        });
      });
    });
    if constexpr (D3 == 1){
      // u*1+0 == lane: already coalesced
      outRow[OFF + lane] = acc[0];
    } else {
      __syncwarp();
      static_for<D3>([&](auto oi){
        constexpr int O = decltype(oi)::value;
        st[lane*D3 + O] = acc[O];          // stride D3 (odd): conflict-free
      });
      __syncwarp();
      static_for<D3>([&](auto ki){
        constexpr int K = decltype(ki)::value;
        outRow[OFF + K*32 + lane] = st[K*32 + lane];   // fully coalesced STG
      });
    }
  });
}

constexpr int ROWS_PER_BLOCK = 8;

__global__ void __launch_bounds__(ROWS_PER_BLOCK*32)
tp_kernel(const float* __restrict__ in1, const float* __restrict__ in2,
          float* __restrict__ out, int nrows){
  __shared__ float stage[ROWS_PER_BLOCK][288];
  const int lane = threadIdx.x & 31;
  const int w    = threadIdx.x >> 5;
  const int row  = blockIdx.x * ROWS_PER_BLOCK + w;
  if(row >= nrows) return;

  const float* x1 = in1 + (size_t)row * 288;
  const float* x2 = in2 + (size_t)row * 9;
  float* outRow   = out + (size_t)row * 2592;

  // input1 chunk layout is (d1, mul): element (m,u) at off1 + m*32 + u, lane==u
  float a[9];
  a[0] = x1[lane];
  a[1] = x1[ 32+lane]; a[2] = x1[ 64+lane]; a[3] = x1[ 96+lane];
  a[4] = x1[128+lane]; a[5] = x1[160+lane]; a[6] = x1[192+lane];
  a[7] = x1[224+lane]; a[8] = x1[256+lane];

  float b[9];
  #pragma unroll
  for(int n=0;n<9;n++) b[n] = __ldg(x2 + n);   // warp-uniform broadcast

  float* st = stage[w];
  do_block<0,0, 0>(a,b,outRow,st,lane);
  do_block<0,1, 1>(a,b,outRow,st,lane);
  do_block<0,2, 2>(a,b,outRow,st,lane);
  do_block<1,0, 3>(a,b,outRow,st,lane);
  do_block<1,1, 4>(a,b,outRow,st,lane);
  do_block<1,2, 7>(a,b,outRow,st,lane);
  do_block<2,0,10>(a,b,outRow,st,lane);
  do_block<2,1,11>(a,b,outRow,st,lane);
  do_block<2,2,14>(a,b,outRow,st,lane);
}

extern "C" void kernel_launch(void* const* d_in, const int* in_sizes, int n_in,
                              void* d_out, int out_size){
  const float* in1 = (const float*)d_in[0];
  const float* in2 = (const float*)d_in[1];
  float* out = (float*)d_out;
  const int nrows = in_sizes[0] / 288;
  const int blocks = (nrows + ROWS_PER_BLOCK - 1) / ROWS_PER_BLOCK;
  tp_kernel<<<blocks, ROWS_PER_BLOCK*32>>>(in1, in2, out, nrows);
}

// round 17
// speedup vs baseline: 1.1256x; 1.1256x over previous
#include <cuda_runtime.h>

// ============================================================================
// Compile-time Clebsch-Gordan / real Wigner-3j tables.
// Bit-for-bit replication of the reference's Racah formula + e3nn real basis
// change, evaluated in constexpr doubles, so every coefficient becomes an
// immediate in SASS and zero entries are eliminated at compile time.
// ============================================================================
namespace cgc {

constexpr double cfact(int n){ double r=1.0; for(int i=2;i<=n;i++) r*=(double)i; return r; }
constexpr double csqrt(double x){
  if(x<=0.0) return 0.0;
  double r = x>1.0? x:1.0;
  for(int i=0;i<60;i++) r = 0.5*(r + x/r);
  return r;
}
constexpr int cmax3(int a,int b,int c){ int m=a>b?a:b; return m>c?m:c; }
constexpr int cmin3(int a,int b,int c){ int m=a<b?a:b; return m<c?m:c; }

constexpr double su2_cg(int j1,int m1,int j2,int m2,int j3,int m3){
  if(m3 != m1+m2) return 0.0;
  int vmin = cmax3(-j1+j2+m3, -j1+m1, 0);
  int vmax = cmin3(j2+j3+m1, j3-j1+j2, j3+m3);
  if(vmax < vmin) return 0.0;
  double C = csqrt((double)(2*j3+1)*cfact(j3+j1-j2)*cfact(j3-j1+j2)*cfact(j1+j2-j3)
                   *cfact(j3+m3)*cfact(j3-m3)
                   /(cfact(j1+j2+j3+1)*cfact(j1-m1)*cfact(j1+m1)*cfact(j2-m2)*cfact(j2+m2)));
  double S=0.0;
  for(int v=vmin; v<=vmax; v++){
    double sgn = ((v+j2+m2)&1)? -1.0: 1.0;
    S += sgn/cfact(v)*cfact(j2+j3+m1-v)*cfact(j1-m1+v)
         /(cfact(j3-j1+j2-v)*cfact(j3+m3-v)*cfact(v+j1-j2-m3));
  }
  return C*S;
}

struct cplx { double re; double im; };
constexpr cplx cmul(cplx a, cplx b){ return cplx{a.re*b.re-a.im*b.im, a.re*b.im+a.im*b.re}; }
constexpr cplx conjc(cplx a){ return cplx{a.re,-a.im}; }

// Sized for max l = 4 (2*l+1 = 9): qmat is used for l1,l2 (<=2) AND l3 (<=4).
struct QMat { cplx v[9][9]; };
constexpr QMat qmat(int l){
  QMat q{};
  double s = 1.0/csqrt(2.0);
  for(int m=-l;m<0;m++){
    q.v[l+m][l-m] = cplx{s,0.0};      // q[l+m, l+|m|] = s
    q.v[l+m][l+m] = cplx{0.0,-s};     // q[l+m, l-|m|] = -i s
  }
  q.v[l][l] = cplx{1.0,0.0};
  for(int m=1;m<=l;m++){
    double sg = (m&1)? -1.0:1.0;
    q.v[l+m][l+m] = cplx{sg*s,0.0};
    q.v[l+m][l-m] = cplx{0.0,sg*s};
  }
  cplx ph{1.0,0.0};
  for(int i=0;i<l;i++) ph = cmul(ph, cplx{0.0,-1.0});   // (-1j)^l
  for(int a=0;a<2*l+1;a++) for(int b=0;b<2*l+1;b++) q.v[a][b] = cmul(ph, q.v[a][b]);
  return q;
}

struct W3J { double v[5][5][9]; };

constexpr W3J wigner3j_scaled(int l1,int l2,int l3){
  cplx C[5][5][9] = {};
  for(int m1=-l1;m1<=l1;m1++)
    for(int m2=-l2;m2<=l2;m2++){
      int m3=m1+m2;
      if(m3>=-l3 && m3<=l3)
        C[l1+m1][l2+m2][l3+m3] = cplx{ su2_cg(l1,m1,l2,m2,l3,m3), 0.0 };
    }
  QMat q1=qmat(l1); QMat q2=qmat(l2); QMat q3=qmat(l3);
  W3J R{};
  double norm2=0.0;
  for(int j=0;j<2*l1+1;j++)
   for(int l=0;l<2*l2+1;l++)
    for(int n=0;n<2*l3+1;n++){
      double sre=0.0;
      for(int i=0;i<2*l1+1;i++){
        if(q1.v[i][j].re==0.0 && q1.v[i][j].im==0.0) continue;
        for(int k=0;k<2*l2+1;k++){
          if(q2.v[k][l].re==0.0 && q2.v[k][l].im==0.0) continue;
          for(int m=0;m<2*l3+1;m++){
            double cr = C[i][k][m].re;
            if(cr==0.0) continue;
            cplx t = cmul(cmul(q1.v[i][j], q2.v[k][l]), conjc(q3.v[m][n]));
            sre += t.re*cr;
          }
        }
      }
      R.v[j][l][n]=sre;
      norm2 += sre*sre;
    }
  double sc = csqrt((double)(2*l3+1))/csqrt(norm2);  // unit-Frobenius, then *sqrt(2l3+1)
  for(int j=0;j<2*l1+1;j++) for(int l=0;l<2*l2+1;l++) for(int n=0;n<2*l3+1;n++)
    R.v[j][l][n]*=sc;
  return R;
}

struct AllCG { W3J p[19]; };
constexpr AllCG build_all(){
  AllCG A{};
  int idx=0;
  for(int l1=0;l1<3;l1++)
    for(int l2=0;l2<3;l2++){
      int lo = l1>l2? l1-l2 : l2-l1;
      for(int l3=lo;l3<=l1+l2;l3++){
        A.p[idx] = wigner3j_scaled(l1,l2,l3);
        idx++;
      }
    }
  return A;
}
constexpr AllCG CG_ALL = build_all();

} // namespace cgc

// Output chunk offsets per path index (e3nn Irreps.sort order of output, precomputed):
// order = [0,4,14, 1,3,7,11,5,15, 2,6,10,16,8,12, 9,13,17, 18], chunk = 32*(2l3+1)
constexpr int OUT_OFF[19] = {0,96,672,192,32,480,832,288,1312,1632,
                             992,384,1472,1856,64,576,1152,2080,2304};

template<int P,int M,int Nn,int O>
__host__ __device__ constexpr float cgf(){
  constexpr double v = cgc::CG_ALL.p[P].v[M][Nn][O];
  return (v>1e-7 || v<-1e-7) ? (float)v : 0.0f;
}

// ---- compile-time loop machinery (indices stay constant expressions) ----
template<int I> struct ic { static constexpr int value = I; };
template<int N,int I=0,class F>
__device__ __forceinline__ void static_for(F&& f){
  if constexpr (I < N){ f(ic<I>{}); static_for<N, I+1>(f); }
}

// One (l1,l2) block: compute all l3 paths.
// Staged paths (D3>1): lane writes its D3 outputs contiguously to SMEM
// (stride D3 odd -> conflict-free STS), one __syncwarp, then the warp reads
// the staged 32*D3 floats as float4 (LDS.128, conflict-free) and stores with
// STG.128 (all OUT_OFF are 128B-aligned). Double-buffered by global staged-path
// parity so the WAR hazard is covered by the NEXT path's sync -> 1 sync/path.
template<int L1,int L2,int P0,int S0>
__device__ __forceinline__ void do_block(const float (&a)[9], const float (&b)[9],
                                         float* __restrict__ outRow,
                                         float* st, int lane){
  constexpr int D1 = 2*L1+1, D2 = 2*L2+1;
  constexpr int AO = (L1==0)?0:((L1==1)?1:4);
  constexpr int BO = (L2==0)?0:((L2==1)?1:4);
  float p[D1*D2];
  static_for<D1*D2>([&](auto mn){
    constexpr int MN = decltype(mn)::value;
    p[MN] = a[AO + MN/D2] * b[BO + MN%D2];
  });
  constexpr int L3LO = (L1>L2)?(L1-L2):(L2-L1);
  static_for<L1+L2-L3LO+1>([&](auto t){
    constexpr int T  = decltype(t)::value;
    constexpr int L3 = L3LO + T;
    constexpr int P  = P0 + T;
    constexpr int D3 = 2*L3+1;
    constexpr int OFF = OUT_OFF[P];
    float acc[D3] = {};
    static_for<D1>([&](auto mi){
      constexpr int M = decltype(mi)::value;
      static_for<D2>([&](auto ni){
        constexpr int Nn = decltype(ni)::value;
        static_for<D3>([&](auto oi){
          constexpr int O = decltype(oi)::value;
          constexpr float c = cgf<P,M,Nn,O>();
          if constexpr (c != 0.0f)
            acc[O] = fmaf(c, p[M*D2+Nn], acc[O]);
        });
      });
    });
    if constexpr (D3 == 1){
      // element index == u == lane: already coalesced
      outRow[OFF + lane] = acc[0];
    } else {
      // global staged-path index (skips D3==1 paths, which only occur at T=0
      // when L1==L2); consecutive staged paths alternate buffers.
      constexpr int SIDX = S0 + T - ((L1==L2) ? 1 : 0);
      float* buf = st + (SIDX & 1) * 288;
      // contiguous per-lane staging: element e = u*D3 + o at buf[e]
      static_for<D3>([&](auto oi){
        constexpr int O = decltype(oi)::value;
        buf[lane*D3 + O] = acc[O];           // stride D3 (odd): conflict-free
      });
      __syncwarp();
      // vectorized coalesced readback + store (16B aligned everywhere)
      const float4* b4 = reinterpret_cast<const float4*>(buf);
      float4* o4 = reinterpret_cast<float4*>(outRow + OFF);
      constexpr int NF4 = 8 * D3;            // 32*D3 floats / 4
      static_for<(NF4 + 31)/32>([&](auto wi){
        constexpr int W = decltype(wi)::value;
        constexpr int REM = NF4 - W*32;
        if constexpr (REM >= 32){
          o4[W*32 + lane] = b4[W*32 + lane];
        } else {
          if (lane < REM) o4[W*32 + lane] = b4[W*32 + lane];
        }
      });
      // WAR on this buffer is protected by the next staged path's __syncwarp
    }
  });
}

constexpr int ROWS_PER_BLOCK = 8;

__global__ void __launch_bounds__(ROWS_PER_BLOCK*32)
tp_kernel(const float* __restrict__ in1, const float* __restrict__ in2,
          float* __restrict__ out, int nrows){
  __shared__ __align__(16) float stage[ROWS_PER_BLOCK][2*288];  // double buffer
  const int lane = threadIdx.x & 31;
  const int w    = threadIdx.x >> 5;
  const int row  = blockIdx.x * ROWS_PER_BLOCK + w;
  if(row >= nrows) return;

  const float* x1 = in1 + (size_t)row * 288;
  const float* x2 = in2 + (size_t)row * 9;
  float* outRow   = out + (size_t)row * 2592;

  // input1 chunk layout is (d1, mul): element (m,u) at off1 + m*32 + u, lane==u
  float a[9];
  a[0] = x1[lane];
  a[1] = x1[ 32+lane]; a[2] = x1[ 64+lane]; a[3] = x1[ 96+lane];
  a[4] = x1[128+lane]; a[5] = x1[160+lane]; a[6] = x1[192+lane];
  a[7] = x1[224+lane]; a[8] = x1[256+lane];

  float b[9];
  #pragma unroll
  for(int n=0;n<9;n++) b[n] = __ldg(x2 + n);   // warp-uniform broadcast

  float* st = stage[w];
  // S0 = number of staged (D3>1) paths before this (l1,l2) block
  do_block<0,0, 0, 0>(a,b,outRow,st,lane);
  do_block<0,1, 1, 0>(a,b,outRow,st,lane);
  do_block<0,2, 2, 1>(a,b,outRow,st,lane);
  do_block<1,0, 3, 2>(a,b,outRow,st,lane);
  do_block<1,1, 4, 3>(a,b,outRow,st,lane);
  do_block<1,2, 7, 5>(a,b,outRow,st,lane);
  do_block<2,0,10, 8>(a,b,outRow,st,lane);
  do_block<2,1,11, 9>(a,b,outRow,st,lane);
  do_block<2,2,14,12>(a,b,outRow,st,lane);
}

extern "C" void kernel_launch(void* const* d_in, const int* in_sizes, int n_in,
                              void* d_out, int out_size){
  const float* in1 = (const float*)d_in[0];
  const float* in2 = (const float*)d_in[1];
  float* out = (float*)d_out;
  const int nrows = in_sizes[0] / 288;
  const int blocks = (nrows + ROWS_PER_BLOCK - 1) / ROWS_PER_BLOCK;
  tp_kernel<<<blocks, ROWS_PER_BLOCK*32>>>(in1, in2, out, nrows);
}